// round 11
// baseline (speedup 1.0000x reference)
#include <cuda_runtime.h>
#include <math.h>
#include <stdint.h>

// ---------------- problem constants ----------------
constexpr int Bn = 4;
constexpr int Tn = 1024;
constexpr int En = 1024;
constexpr int Hn = 16;
constexpr int Dn = 64;
constexpr int Ln = 8;
constexpr int FFn = 4096;
constexpr int Vn = 50257;
constexpr int VPAD = 50432;           // 197 * 256
constexpr int BT = Bn * Tn;
constexpr float EPS = 1e-5f;
constexpr float SCALE = 0.03125f;     // E^-0.5

// ---------------- scratch (device globals) ----------------
__device__ float g_x   [BT * En];
__device__ float g_h   [BT * En];
__device__ float g_qkv [BT * 3 * En];          // [BT][3072]: q | k | v (head-concat)
__device__ float g_att [BT * En];
__device__ float g_ff  [BT * FFn];
__device__ float g_wqkv[Ln * En * 3 * En];     // [L][E][3*H*D] rounded
__device__ float g_wprj[Ln * En * En];         // rounded copy of w_proj
__device__ float g_wff1[Ln * En * FFn];        // rounded
__device__ float g_wff2[Ln * FFn * En];        // rounded
__device__ float g_wpad[En * VPAD];            // padded + rounded lm_w
__device__ float g_rownll[BT];

// ---------------- PTX helpers ----------------
__device__ __forceinline__ void cp16(uint32_t dst, const void* src) {
    asm volatile("cp.async.cg.shared.global [%0], [%1], 16;\n" :: "r"(dst), "l"(src));
}
__device__ __forceinline__ void cp_commit() { asm volatile("cp.async.commit_group;\n" ::); }
template<int N> __device__ __forceinline__ void cp_wait() {
    asm volatile("cp.async.wait_group %0;\n" :: "n"(N));
}
__device__ __forceinline__ float rnd_tf32(float x) {
    uint32_t u;
    asm("cvt.rna.tf32.f32 %0, %1;" : "=r"(u) : "f"(x));
    return __uint_as_float(u);
}
__device__ __forceinline__ void mma8(float* c, const uint32_t* a, const uint32_t* b) {
    asm volatile(
        "mma.sync.aligned.m16n8k8.row.col.f32.tf32.tf32.f32 "
        "{%0,%1,%2,%3}, {%4,%5,%6,%7}, {%8,%9}, {%0,%1,%2,%3};\n"
        : "+f"(c[0]), "+f"(c[1]), "+f"(c[2]), "+f"(c[3])
        : "r"(a[0]), "r"(a[1]), "r"(a[2]), "r"(a[3]), "r"(b[0]), "r"(b[1]));
}

// ---------------- tf32 GEMM (inputs pre-rounded; no cvt in loop) ----------------
// 8 warps / 256 threads; CTA tile 128x256; warp tile 64x64 -> 32 MMAs per 32 LDS per ks.
// flags: bit0 = relu, bit1 = round output to tf32
template<int BM, int BN, int WM, int WN, int BK>
__global__ void __launch_bounds__((BM / WM) * (BN / WN) * 32, 1)
gemm_tf32(int M, int N, int K,
          const float* __restrict__ A, int lda,
          const float* __restrict__ Bm, int ldb,
          float* __restrict__ C, int ldc,
          const float* __restrict__ bias, const float* __restrict__ residual,
          int flags)
{
    extern __shared__ float smem[];
    constexpr int THREADS = (BM / WM) * (BN / WN) * 32;
    constexpr int ASTR   = BK + 4;
    constexpr int BSTR   = BN + 8;
    constexpr int A_TILE = BM * ASTR;
    constexpr int B_TILE = BK * BSTR;
    constexpr int MT = WM / 16, NT = WN / 8;
    constexpr int KV = BK / 4;

    float* As = smem;
    float* Bs = smem + 2 * A_TILE;

    const int tid  = threadIdx.x;
    const int lane = tid & 31, wid = tid >> 5;
    const int m0 = blockIdx.x * BM, n0 = blockIdx.y * BN;
    constexpr int WNC = BN / WN;
    const int wm = wid / WNC, wn = wid % WNC;
    const int qr = lane >> 2, qc = lane & 3;

    float acc[MT][NT][4];
#pragma unroll
    for (int i = 0; i < MT; i++)
#pragma unroll
        for (int j = 0; j < NT; j++)
#pragma unroll
            for (int r = 0; r < 4; r++) acc[i][j][r] = 0.f;

    const uint32_t sA = (uint32_t)__cvta_generic_to_shared(As);
    const uint32_t sB = (uint32_t)__cvta_generic_to_shared(Bs);

    auto load_A = [&](int s, int k0) {
#pragma unroll
        for (int i = 0; i < (BM * KV) / THREADS; i++) {
            int e   = tid + i * THREADS;
            int row = e / KV;
            int kc  = (e % KV) * 4;
            cp16(sA + (uint32_t)(s * A_TILE + row * ASTR + kc) * 4u,
                 A + (long long)(m0 + row) * lda + k0 + kc);
        }
    };
    auto load_B = [&](int s, int k0) {
#pragma unroll
        for (int i = 0; i < (BK * (BN / 4)) / THREADS; i++) {
            int e  = tid + i * THREADS;
            int k  = e / (BN / 4);
            int nc = (e % (BN / 4)) * 4;
            cp16(sB + (uint32_t)(s * B_TILE + k * BSTR + nc) * 4u,
                 Bm + (long long)(k0 + k) * ldb + n0 + nc);
        }
    };

    const int iters = K / BK;
    load_A(0, 0); load_B(0, 0);
    cp_commit();

    for (int it = 0; it < iters; it++) {
        const int s = it & 1;
        if (it + 1 < iters) {
            load_A(s ^ 1, (it + 1) * BK);
            load_B(s ^ 1, (it + 1) * BK);
            cp_commit();
            cp_wait<1>();
        } else {
            cp_wait<0>();
        }
        __syncthreads();

        const float* Ab = As + s * A_TILE;
        const float* Bb = Bs + s * B_TILE;
#pragma unroll
        for (int ks = 0; ks < BK; ks += 8) {
            uint32_t af[MT][4], bf[NT][2];
#pragma unroll
            for (int mt = 0; mt < MT; mt++) {
                int r0 = wm * WM + mt * 16 + qr;
                af[mt][0] = __float_as_uint(Ab[r0 * ASTR + ks + qc]);
                af[mt][1] = __float_as_uint(Ab[(r0 + 8) * ASTR + ks + qc]);
                af[mt][2] = __float_as_uint(Ab[r0 * ASTR + ks + qc + 4]);
                af[mt][3] = __float_as_uint(Ab[(r0 + 8) * ASTR + ks + qc + 4]);
            }
#pragma unroll
            for (int nt = 0; nt < NT; nt++) {
                int cn = wn * WN + nt * 8 + qr;
                bf[nt][0] = __float_as_uint(Bb[(ks + qc) * BSTR + cn]);
                bf[nt][1] = __float_as_uint(Bb[(ks + qc + 4) * BSTR + cn]);
            }
#pragma unroll
            for (int mt = 0; mt < MT; mt++)
#pragma unroll
                for (int nt = 0; nt < NT; nt++)
                    mma8(acc[mt][nt], af[mt], bf[nt]);
        }
        __syncthreads();
    }

    const int relu = flags & 1, roundo = flags & 2;
#pragma unroll
    for (int mt = 0; mt < MT; mt++) {
#pragma unroll
        for (int nt = 0; nt < NT; nt++) {
            int r = m0 + wm * WM + mt * 16 + qr;
            int c = n0 + wn * WN + nt * 8 + 2 * qc;
#pragma unroll
            for (int v = 0; v < 4; v++) {
                int rr = r + (v >> 1) * 8;
                int cc = c + (v & 1);
                if (cc >= N) continue;
                float val = acc[mt][nt][v];
                if (bias) val += bias[cc];
                long long off = (long long)rr * ldc + cc;
                if (residual) val += residual[off];
                if (relu) val = fmaxf(val, 0.f);
                if (roundo) val = rnd_tf32(val);
                C[off] = val;
            }
        }
    }
}

// ---------------- fused causal flash attention (tf32 mma) ----------------
constexpr int FBR = 128, FBC = 64;
constexpr int QSTR = 68, KSTR = 68, VSTR = 72, PSTR = 68;
constexpr int FLASH_SMEM = (FBR * QSTR + FBC * KSTR + FBC * VSTR) * 4;  // 70656

__global__ void __launch_bounds__(256)
flash_kernel(const float* __restrict__ qkv, float* __restrict__ att)
{
    extern __shared__ float sm[];
    float* Ps = sm;                         // Q staging, then P
    float* Ks = sm + FBR * QSTR;
    float* Vs = Ks + FBC * KSTR;

    const int ib = 7 - blockIdx.x;          // heavy blocks first
    const int bh = blockIdx.y;
    const int b = bh >> 4, h = bh & 15;
    const int tid = threadIdx.x, lane = tid & 31, w = tid >> 5;
    const int qr = lane >> 2, qc = lane & 3;

    const float* qbase = qkv + (long long)b * Tn * 3072 + h * 64;
    const float* kbase = qbase + 1024;
    const float* vbase = qbase + 2048;

    {
        uint32_t sQ = (uint32_t)__cvta_generic_to_shared(Ps);
        for (int e = tid; e < FBR * 16; e += 256) {
            int r = e >> 4, c4 = (e & 15) << 2;
            cp16(sQ + (uint32_t)(r * QSTR + c4) * 4u,
                 qbase + (long long)(ib * FBR + r) * 3072 + c4);
        }
        cp_commit(); cp_wait<0>();
    }
    __syncthreads();

    uint32_t qf[8][4];
    {
        const float* Qb = Ps + (w * 16 + qr) * QSTR;
#pragma unroll
        for (int ks = 0; ks < 8; ks++) {
            qf[ks][0] = __float_as_uint(Qb[ks * 8 + qc]);
            qf[ks][1] = __float_as_uint(Qb[8 * QSTR + ks * 8 + qc]);
            qf[ks][2] = __float_as_uint(Qb[ks * 8 + qc + 4]);
            qf[ks][3] = __float_as_uint(Qb[8 * QSTR + ks * 8 + qc + 4]);
        }
    }

    float m0 = -1e30f, m1 = -1e30f, l0 = 0.f, l1 = 0.f;
    float o[8][4];
#pragma unroll
    for (int i = 0; i < 8; i++)
#pragma unroll
        for (int v = 0; v < 4; v++) o[i][v] = 0.f;

    const uint32_t sK = (uint32_t)__cvta_generic_to_shared(Ks);
    const uint32_t sV = (uint32_t)__cvta_generic_to_shared(Vs);
    const int row0 = ib * FBR + w * 16 + qr;
    const int jmax = 2 * ib + 2;

    for (int j = 0; j < jmax; j++) {
        __syncthreads();
        for (int e = tid; e < FBC * 16; e += 256) {
            int r = e >> 4, c4 = (e & 15) << 2;
            cp16(sK + (uint32_t)(r * KSTR + c4) * 4u,
                 kbase + (long long)(j * FBC + r) * 3072 + c4);
        }
        for (int e = tid; e < FBC * 16; e += 256) {
            int r = e >> 4, c4 = (e & 15) << 2;
            cp16(sV + (uint32_t)(r * VSTR + c4) * 4u,
                 vbase + (long long)(j * FBC + r) * 3072 + c4);
        }
        cp_commit(); cp_wait<0>();
        __syncthreads();

        float s[8][4];
#pragma unroll
        for (int nt = 0; nt < 8; nt++)
#pragma unroll
            for (int v = 0; v < 4; v++) s[nt][v] = 0.f;
#pragma unroll
        for (int ks = 0; ks < 8; ks++) {
            uint32_t bf[8][2];
#pragma unroll
            for (int nt = 0; nt < 8; nt++) {
                const float* Kr = Ks + (nt * 8 + qr) * KSTR + ks * 8 + qc;
                bf[nt][0] = __float_as_uint(Kr[0]);
                bf[nt][1] = __float_as_uint(Kr[4]);
            }
#pragma unroll
            for (int nt = 0; nt < 8; nt++)
                mma8(s[nt], qf[ks], bf[nt]);
        }

#pragma unroll
        for (int nt = 0; nt < 8; nt++) {
            int c0 = j * FBC + nt * 8 + 2 * qc;
#pragma unroll
            for (int v = 0; v < 4; v++) {
                int cg = c0 + (v & 1);
                int rg = row0 + (v >> 1) * 8;
                float val = s[nt][v] * SCALE;
                s[nt][v] = (cg <= rg) ? val : -1e30f;
            }
        }

        float rm0 = -1e30f, rm1 = -1e30f;
#pragma unroll
        for (int nt = 0; nt < 8; nt++) {
            rm0 = fmaxf(rm0, fmaxf(s[nt][0], s[nt][1]));
            rm1 = fmaxf(rm1, fmaxf(s[nt][2], s[nt][3]));
        }
        rm0 = fmaxf(rm0, __shfl_xor_sync(0xffffffffu, rm0, 1));
        rm0 = fmaxf(rm0, __shfl_xor_sync(0xffffffffu, rm0, 2));
        rm1 = fmaxf(rm1, __shfl_xor_sync(0xffffffffu, rm1, 1));
        rm1 = fmaxf(rm1, __shfl_xor_sync(0xffffffffu, rm1, 2));
        float nm0 = fmaxf(m0, rm0), nm1 = fmaxf(m1, rm1);
        float a0 = __expf(m0 - nm0), a1 = __expf(m1 - nm1);

        float* Pr = Ps + (w * 16 + qr) * PSTR;
        float sum0 = 0.f, sum1 = 0.f;
#pragma unroll
        for (int nt = 0; nt < 8; nt++) {
            float p0 = __expf(s[nt][0] - nm0);
            float p1 = __expf(s[nt][1] - nm0);
            float p2 = __expf(s[nt][2] - nm1);
            float p3 = __expf(s[nt][3] - nm1);
            sum0 += p0 + p1; sum1 += p2 + p3;
            int c = nt * 8 + 2 * qc;
            Pr[c]     = rnd_tf32(p0);
            Pr[c + 1] = rnd_tf32(p1);
            Pr[8 * PSTR + c]     = rnd_tf32(p2);
            Pr[8 * PSTR + c + 1] = rnd_tf32(p3);
        }
        sum0 += __shfl_xor_sync(0xffffffffu, sum0, 1);
        sum0 += __shfl_xor_sync(0xffffffffu, sum0, 2);
        sum1 += __shfl_xor_sync(0xffffffffu, sum1, 1);
        sum1 += __shfl_xor_sync(0xffffffffu, sum1, 2);
        l0 = l0 * a0 + sum0;
        l1 = l1 * a1 + sum1;
        m0 = nm0; m1 = nm1;
#pragma unroll
        for (int nto = 0; nto < 8; nto++) {
            o[nto][0] *= a0; o[nto][1] *= a0;
            o[nto][2] *= a1; o[nto][3] *= a1;
        }
        __syncwarp();

#pragma unroll
        for (int ks = 0; ks < 8; ks++) {
            uint32_t pf[4];
            pf[0] = __float_as_uint(Pr[ks * 8 + qc]);
            pf[1] = __float_as_uint(Pr[8 * PSTR + ks * 8 + qc]);
            pf[2] = __float_as_uint(Pr[ks * 8 + qc + 4]);
            pf[3] = __float_as_uint(Pr[8 * PSTR + ks * 8 + qc + 4]);
#pragma unroll
            for (int nto = 0; nto < 8; nto++) {
                uint32_t bf2[2];
                bf2[0] = __float_as_uint(Vs[(ks * 8 + qc) * VSTR + nto * 8 + qr]);
                bf2[1] = __float_as_uint(Vs[(ks * 8 + qc + 4) * VSTR + nto * 8 + qr]);
                mma8(o[nto], pf, bf2);
            }
        }
        __syncwarp();
    }

    float i0 = 1.f / l0, i1 = 1.f / l1;
    float* arow0 = att + (long long)(b * Tn + row0) * En + h * 64;
    float* arow1 = arow0 + 8ll * En;
#pragma unroll
    for (int nto = 0; nto < 8; nto++) {
        int c = nto * 8 + 2 * qc;
        float2 v0 = { rnd_tf32(o[nto][0] * i0), rnd_tf32(o[nto][1] * i0) };
        float2 v1 = { rnd_tf32(o[nto][2] * i1), rnd_tf32(o[nto][3] * i1) };
        *(float2*)(arow0 + c) = v0;
        *(float2*)(arow1 + c) = v1;
    }
}

// ---------------- weight prep ----------------
__global__ void round_copy(const float* __restrict__ src, float* __restrict__ dst, long long n4)
{
    long long i = (long long)blockIdx.x * blockDim.x + threadIdx.x;
    if (i >= n4) return;
    float4 v = ((const float4*)src)[i];
    v.x = rnd_tf32(v.x); v.y = rnd_tf32(v.y); v.z = rnd_tf32(v.z); v.w = rnd_tf32(v.w);
    ((float4*)dst)[i] = v;
}

__global__ void repack_qkv(const float* __restrict__ wq,
                           const float* __restrict__ wk,
                           const float* __restrict__ wv,
                           float* __restrict__ dst)
{
    int le = blockIdx.x;            // l*1024 + e
    int l = le >> 10, e = le & 1023;
    const float* srcs[3] = { wq, wk, wv };
    float* drow = dst + (long long)le * 3072;
    for (int s = 0; s < 3; s++) {
        const float* ws = srcs[s];
        for (int idx = threadIdx.x; idx < 1024; idx += 256) {
            int h = idx >> 6, d = idx & 63;
            float v = ws[(((long long)l * Hn + h) * En + e) * Dn + d];
            drow[s * 1024 + idx] = rnd_tf32(v);
        }
    }
}

__global__ void pad_lm_w(const float* __restrict__ src, float* __restrict__ dst)
{
    int r = blockIdx.x;
    const float* s = src + (long long)r * Vn;
    float* d = dst + (long long)r * VPAD;
    for (int c = threadIdx.x; c < VPAD; c += blockDim.x)
        d[c] = (c < Vn) ? rnd_tf32(s[c]) : 0.f;
}

// ---------------- elementwise ----------------
__global__ void embed_kernel(const int* __restrict__ idx,
                             const float* __restrict__ tok,
                             const float* __restrict__ pos,
                             float* __restrict__ x)
{
    int bt = blockIdx.x;
    int t = bt % Tn;
    int token = idx[bt];
    const float4* tr = (const float4*)(tok + (long long)token * En);
    const float4* pr = (const float4*)(pos + (long long)t * En);
    float4* xr = (float4*)(x + (long long)bt * En);
    int e = threadIdx.x;
    float4 a = tr[e], b = pr[e];
    xr[e] = make_float4(a.x + b.x, a.y + b.y, a.z + b.z, a.w + b.w);
}

__global__ void ln_kernel(const float* __restrict__ x,
                          const float* __restrict__ g,
                          const float* __restrict__ b,
                          float* __restrict__ out)
{
    int row = blockIdx.x;
    int tid = threadIdx.x, lane = tid & 31, w = tid >> 5;
    const float4* xr = (const float4*)(x + (long long)row * En);
    float4 v = xr[tid];
    __shared__ float red[8];

    float s = v.x + v.y + v.z + v.w;
#pragma unroll
    for (int o = 16; o > 0; o >>= 1) s += __shfl_xor_sync(0xffffffffu, s, o);
    if (lane == 0) red[w] = s;
    __syncthreads();
    float mu = (red[0]+red[1]+red[2]+red[3]+red[4]+red[5]+red[6]+red[7]) * (1.f / En);

    float dx = v.x - mu, dy = v.y - mu, dz = v.z - mu, dw = v.w - mu;
    float vv = dx*dx + dy*dy + dz*dz + dw*dw;
#pragma unroll
    for (int o = 16; o > 0; o >>= 1) vv += __shfl_xor_sync(0xffffffffu, vv, o);
    __syncthreads();
    if (lane == 0) red[w] = vv;
    __syncthreads();
    float rstd = rsqrtf((red[0]+red[1]+red[2]+red[3]+red[4]+red[5]+red[6]+red[7]) * (1.f / En) + EPS);

    const float4 gg = ((const float4*)g)[tid];
    const float4 bb = ((const float4*)b)[tid];
    float4 o4;
    o4.x = rnd_tf32(dx * rstd * gg.x + bb.x);
    o4.y = rnd_tf32(dy * rstd * gg.y + bb.y);
    o4.z = rnd_tf32(dz * rstd * gg.z + bb.z);
    o4.w = rnd_tf32(dw * rstd * gg.w + bb.w);
    ((float4*)(out + (long long)row * En))[tid] = o4;
}

__global__ void nll_kernel(const float* __restrict__ logits,
                           const int* __restrict__ targets,
                           float* __restrict__ rownll)
{
    int row = blockIdx.x;
    const float* lr = logits + (long long)row * Vn;
    int tid = threadIdx.x;
    float m = -1e30f, s = 0.f;
    for (int i = tid; i < Vn; i += 256) {
        float v = lr[i];
        if (v > m) { s = s * __expf(m - v) + 1.f; m = v; }
        else       { s += __expf(v - m); }
    }
    __shared__ float sm2[256], ss[256];
    sm2[tid] = m; ss[tid] = s;
    __syncthreads();
    for (int o = 128; o > 0; o >>= 1) {
        if (tid < o) {
            float m2 = sm2[tid + o], s2 = ss[tid + o];
            float M = fmaxf(sm2[tid], m2);
            ss[tid] = ss[tid] * __expf(sm2[tid] - M) + s2 * __expf(m2 - M);
            sm2[tid] = M;
        }
        __syncthreads();
    }
    if (tid == 0) {
        float lse = sm2[0] + logf(ss[0]);
        rownll[row] = -(lr[targets[row]] - lse);
    }
}

__global__ void mean_kernel(const float* __restrict__ rownll, float* __restrict__ out)
{
    __shared__ float red[256];
    int tid = threadIdx.x;
    float s = 0.f;
    for (int i = tid; i < BT; i += 256) s += rownll[i];
    red[tid] = s; __syncthreads();
    for (int o = 128; o > 0; o >>= 1) { if (tid < o) red[tid] += red[tid + o]; __syncthreads(); }
    if (tid == 0) out[0] = red[0] / (float)BT;
}

// ---------------- host launcher ----------------
// BM=128 BN=256 WM=64 WN=64 BK=32: smem = 2*(128*36 + 32*264)*4 = 104448
static constexpr int SMEM_A = 2 * (128 * 36 + 32 * 264) * 4;

extern "C" void kernel_launch(void* const* d_in, const int* in_sizes, int n_in,
                              void* d_out, int out_size)
{
    const int*   idx     = (const int*)  d_in[0];
    const int*   targets = (const int*)  d_in[1];
    const float* tok_emb = (const float*)d_in[2];
    const float* pos_emb = (const float*)d_in[3];
    const float* wq      = (const float*)d_in[4];
    const float* wk      = (const float*)d_in[5];
    const float* wv      = (const float*)d_in[6];
    const float* w_proj  = (const float*)d_in[7];
    const float* b_proj  = (const float*)d_in[8];
    const float* ln1_g   = (const float*)d_in[9];
    const float* ln1_b   = (const float*)d_in[10];
    const float* ln2_g   = (const float*)d_in[11];
    const float* ln2_b   = (const float*)d_in[12];
    const float* ff_w1   = (const float*)d_in[13];
    const float* ff_b1   = (const float*)d_in[14];
    const float* ff_w2   = (const float*)d_in[15];
    const float* ff_b2   = (const float*)d_in[16];
    const float* lnf_g   = (const float*)d_in[17];
    const float* lnf_b   = (const float*)d_in[18];
    const float* lm_w    = (const float*)d_in[19];
    const float* lm_b    = (const float*)d_in[20];
    float* out = (float*)d_out;

    float *x, *h, *qkv, *att, *ff, *wqkv, *wprj, *wff1, *wff2, *wpad, *rownll;
    cudaGetSymbolAddress((void**)&x,      g_x);
    cudaGetSymbolAddress((void**)&h,      g_h);
    cudaGetSymbolAddress((void**)&qkv,    g_qkv);
    cudaGetSymbolAddress((void**)&att,    g_att);
    cudaGetSymbolAddress((void**)&ff,     g_ff);
    cudaGetSymbolAddress((void**)&wqkv,   g_wqkv);
    cudaGetSymbolAddress((void**)&wprj,   g_wprj);
    cudaGetSymbolAddress((void**)&wff1,   g_wff1);
    cudaGetSymbolAddress((void**)&wff2,   g_wff2);
    cudaGetSymbolAddress((void**)&wpad,   g_wpad);
    cudaGetSymbolAddress((void**)&rownll, g_rownll);

    auto kA = gemm_tf32<128, 256, 64, 64, 32>;   // 8 warps / 256 threads
    cudaFuncSetAttribute(kA, cudaFuncAttributeMaxDynamicSharedMemorySize, SMEM_A);
    cudaFuncSetAttribute(flash_kernel, cudaFuncAttributeMaxDynamicSharedMemorySize, FLASH_SMEM);

    // ---- weight prep ----
    repack_qkv<<<Ln * En, 256>>>(wq, wk, wv, wqkv);
    {
        long long n4;
        n4 = (long long)Ln * En * En / 4;
        round_copy<<<(unsigned)((n4 + 255) / 256), 256>>>(w_proj, wprj, n4);
        n4 = (long long)Ln * En * FFn / 4;
        round_copy<<<(unsigned)((n4 + 255) / 256), 256>>>(ff_w1, wff1, n4);
        round_copy<<<(unsigned)((n4 + 255) / 256), 256>>>(ff_w2, wff2, n4);
    }
    pad_lm_w<<<En, 256>>>(lm_w, wpad);

    // x = tok_emb[idx] + pos_emb
    embed_kernel<<<BT, 256>>>(idx, tok_emb, pos_emb, x);

    for (int l = 0; l < Ln; l++) {
        // h = LN1(x)
        ln_kernel<<<BT, 256>>>(x, ln1_g + (long long)l * En, ln1_b + (long long)l * En, h);

        // qkv = h @ Wqkv  [4096 x 3072 x 1024]
        kA<<<dim3(BT / 128, 3 * En / 256), 256, SMEM_A>>>(
            BT, 3 * En, En,
            h, En,
            wqkv + (long long)l * En * 3 * En, 3 * En,
            qkv, 3 * En,
            nullptr, nullptr, 2);

        // fused causal attention
        flash_kernel<<<dim3(8, Bn * Hn), 256, FLASH_SMEM>>>(qkv, att);

        // x = x + att @ w_proj + b_proj
        kA<<<dim3(BT / 128, En / 256), 256, SMEM_A>>>(
            BT, En, En,
            att, En,
            wprj + (long long)l * En * En, En,
            x, En,
            b_proj + (long long)l * En, x, 0);

        // h = LN2(x)
        ln_kernel<<<BT, 256>>>(x, ln2_g + (long long)l * En, ln2_b + (long long)l * En, h);

        // ff = relu(h @ ff_w1 + ff_b1)
        kA<<<dim3(BT / 128, FFn / 256), 256, SMEM_A>>>(
            BT, FFn, En,
            h, En,
            wff1 + (long long)l * En * FFn, FFn,
            ff, FFn,
            ff_b1 + (long long)l * FFn, nullptr, 3);

        // x = x + ff @ ff_w2 + ff_b2
        kA<<<dim3(BT / 128, En / 256), 256, SMEM_A>>>(
            BT, En, FFn,
            ff, FFn,
            wff2 + (long long)l * FFn * En, En,
            x, En,
            ff_b2 + (long long)l * En, x, 0);
    }

    // h = LN_f(x)
    ln_kernel<<<BT, 256>>>(x, lnf_g, lnf_b, h);

    // logits = h @ lm_w + lm_b
    kA<<<dim3(BT / 128, VPAD / 256), 256, SMEM_A>>>(
        BT, Vn, En,
        h, En,
        wpad, VPAD,
        out, Vn,
        lm_b, nullptr, 0);

    // loss
    if ((long long)out_size > (long long)BT * Vn) {
        nll_kernel<<<BT, 256>>>(out, targets, rownll);
        mean_kernel<<<1, 256>>>(rownll, out + (long long)BT * Vn);
    }
}

// round 12
// speedup vs baseline: 1.1476x; 1.1476x over previous
#include <cuda_runtime.h>
#include <math.h>
#include <stdint.h>

// ---------------- problem constants ----------------
constexpr int Bn = 4;
constexpr int Tn = 1024;
constexpr int En = 1024;
constexpr int Hn = 16;
constexpr int Dn = 64;
constexpr int Ln = 8;
constexpr int FFn = 4096;
constexpr int Vn = 50257;
constexpr int VPAD = 50304;
constexpr int BT = Bn * Tn;
constexpr float EPS = 1e-5f;
constexpr float SCALE = 0.03125f;     // E^-0.5

// ---------------- scratch (device globals) ----------------
__device__ float g_x   [BT * En];
__device__ float g_h   [BT * En];
__device__ float g_qkv [BT * 3 * En];          // [BT][3072]: q | k | v (head-concat)
__device__ float g_att [BT * En];
__device__ float g_ff  [BT * FFn];
__device__ float g_wqkv[Ln * En * 3 * En];     // [L][E][3*H*D] rounded
__device__ float g_wprj[Ln * En * En];         // rounded copy of w_proj
__device__ float g_wff1[Ln * En * FFn];        // rounded
__device__ float g_wff2[Ln * FFn * En];        // rounded
__device__ float g_wpad[En * VPAD];            // padded + rounded lm_w
__device__ float g_rownll[BT];

// ---------------- PTX helpers ----------------
__device__ __forceinline__ void cp16(uint32_t dst, const void* src) {
    asm volatile("cp.async.cg.shared.global [%0], [%1], 16;\n" :: "r"(dst), "l"(src));
}
__device__ __forceinline__ void cp_commit() { asm volatile("cp.async.commit_group;\n" ::); }
template<int N> __device__ __forceinline__ void cp_wait() {
    asm volatile("cp.async.wait_group %0;\n" :: "n"(N));
}
__device__ __forceinline__ float rnd_tf32(float x) {
    uint32_t u;
    asm("cvt.rna.tf32.f32 %0, %1;" : "=r"(u) : "f"(x));
    return __uint_as_float(u);
}
__device__ __forceinline__ void mma8(float* c, const uint32_t* a, const uint32_t* b) {
    asm volatile(
        "mma.sync.aligned.m16n8k8.row.col.f32.tf32.tf32.f32 "
        "{%0,%1,%2,%3}, {%4,%5,%6,%7}, {%8,%9}, {%0,%1,%2,%3};\n"
        : "+f"(c[0]), "+f"(c[1]), "+f"(c[2]), "+f"(c[3])
        : "r"(a[0]), "r"(a[1]), "r"(a[2]), "r"(a[3]), "r"(b[0]), "r"(b[1]));
}

// ---------------- tf32 GEMM (EXACT R5 config: the 9256us version) ----------------
// 8 warps / 256 threads, warp tile 64x32, 2 CTAs/SM.
// flags: bit0 = relu, bit1 = round output to tf32
template<int BM, int BN, int WM, int WN, int BK>
__global__ void __launch_bounds__(256)
gemm_tf32(int M, int N, int K,
          const float* __restrict__ A, int lda,
          const float* __restrict__ Bm, int ldb,
          float* __restrict__ C, int ldc,
          const float* __restrict__ bias, const float* __restrict__ residual,
          int flags)
{
    extern __shared__ float smem[];
    constexpr int ASTR   = BK + 4;
    constexpr int BSTR   = BN + 8;
    constexpr int A_TILE = BM * ASTR;
    constexpr int B_TILE = BK * BSTR;
    constexpr int MT = WM / 16, NT = WN / 8;
    constexpr int KV = BK / 4;

    float* As = smem;
    float* Bs = smem + 2 * A_TILE;

    const int tid  = threadIdx.x;
    const int lane = tid & 31, wid = tid >> 5;
    const int m0 = blockIdx.x * BM, n0 = blockIdx.y * BN;
    constexpr int WNC = BN / WN;
    const int wm = wid / WNC, wn = wid % WNC;
    const int qr = lane >> 2, qc = lane & 3;

    float acc[MT][NT][4];
#pragma unroll
    for (int i = 0; i < MT; i++)
#pragma unroll
        for (int j = 0; j < NT; j++)
#pragma unroll
            for (int r = 0; r < 4; r++) acc[i][j][r] = 0.f;

    const uint32_t sA = (uint32_t)__cvta_generic_to_shared(As);
    const uint32_t sB = (uint32_t)__cvta_generic_to_shared(Bs);

    auto load_A = [&](int s, int k0) {
#pragma unroll
        for (int i = 0; i < (BM * KV) / 256; i++) {
            int e   = tid + i * 256;
            int row = e / KV;
            int kc  = (e % KV) * 4;
            cp16(sA + (uint32_t)(s * A_TILE + row * ASTR + kc) * 4u,
                 A + (long long)(m0 + row) * lda + k0 + kc);
        }
    };
    auto load_B = [&](int s, int k0) {
#pragma unroll
        for (int i = 0; i < (BK * (BN / 4)) / 256; i++) {
            int e  = tid + i * 256;
            int k  = e / (BN / 4);
            int nc = (e % (BN / 4)) * 4;
            cp16(sB + (uint32_t)(s * B_TILE + k * BSTR + nc) * 4u,
                 Bm + (long long)(k0 + k) * ldb + n0 + nc);
        }
    };

    const int iters = K / BK;
    load_A(0, 0); load_B(0, 0);
    cp_commit();

    for (int it = 0; it < iters; it++) {
        const int s = it & 1;
        if (it + 1 < iters) {
            load_A(s ^ 1, (it + 1) * BK);
            load_B(s ^ 1, (it + 1) * BK);
            cp_commit();
            cp_wait<1>();
        } else {
            cp_wait<0>();
        }
        __syncthreads();

        const float* Ab = As + s * A_TILE;
        const float* Bb = Bs + s * B_TILE;
#pragma unroll
        for (int ks = 0; ks < BK; ks += 8) {
            uint32_t af[MT][4], bf[NT][2];
#pragma unroll
            for (int mt = 0; mt < MT; mt++) {
                int r0 = wm * WM + mt * 16 + qr;
                af[mt][0] = __float_as_uint(Ab[r0 * ASTR + ks + qc]);
                af[mt][1] = __float_as_uint(Ab[(r0 + 8) * ASTR + ks + qc]);
                af[mt][2] = __float_as_uint(Ab[r0 * ASTR + ks + qc + 4]);
                af[mt][3] = __float_as_uint(Ab[(r0 + 8) * ASTR + ks + qc + 4]);
            }
#pragma unroll
            for (int nt = 0; nt < NT; nt++) {
                int cn = wn * WN + nt * 8 + qr;
                bf[nt][0] = __float_as_uint(Bb[(ks + qc) * BSTR + cn]);
                bf[nt][1] = __float_as_uint(Bb[(ks + qc + 4) * BSTR + cn]);
            }
#pragma unroll
            for (int mt = 0; mt < MT; mt++)
#pragma unroll
                for (int nt = 0; nt < NT; nt++)
                    mma8(acc[mt][nt], af[mt], bf[nt]);
        }
        __syncthreads();
    }

    const int relu = flags & 1, roundo = flags & 2;
#pragma unroll
    for (int mt = 0; mt < MT; mt++) {
#pragma unroll
        for (int nt = 0; nt < NT; nt++) {
            int r = m0 + wm * WM + mt * 16 + qr;
            int c = n0 + wn * WN + nt * 8 + 2 * qc;
#pragma unroll
            for (int v = 0; v < 4; v++) {
                int rr = r + (v >> 1) * 8;
                int cc = c + (v & 1);
                if (cc >= N) continue;
                float val = acc[mt][nt][v];
                if (bias) val += bias[cc];
                long long off = (long long)rr * ldc + cc;
                if (residual) val += residual[off];
                if (relu) val = fmaxf(val, 0.f);
                if (roundo) val = rnd_tf32(val);
                C[off] = val;
            }
        }
    }
}

// ---------------- fused causal flash attention (tf32 mma, double-buffered K/V) ----------------
constexpr int FBR = 128, FBC = 64;
constexpr int QSTR = 68, KSTR = 68, VSTR = 72, PSTR = 68;
constexpr int KV_TILE = FBC * KSTR;     // one K buffer (floats)
constexpr int V_TILE  = FBC * VSTR;     // one V buffer (floats)
constexpr int FLASH_SMEM = (FBR * QSTR + 2 * KV_TILE + 2 * V_TILE) * 4;  // 106496

__global__ void __launch_bounds__(256)
flash_kernel(const float* __restrict__ qkv, float* __restrict__ att)
{
    extern __shared__ float sm[];
    float* Ps = sm;                          // Q staging, then P
    float* Kbase = sm + FBR * QSTR;          // K0 | K1
    float* Vbase = Kbase + 2 * KV_TILE;      // V0 | V1

    const int ib = 7 - blockIdx.x;           // heavy blocks first
    const int bh = blockIdx.y;
    const int b = bh >> 4, h = bh & 15;
    const int tid = threadIdx.x, lane = tid & 31, w = tid >> 5;
    const int qr = lane >> 2, qc = lane & 3;

    const float* qbase = qkv + (long long)b * Tn * 3072 + h * 64;
    const float* kbase = qbase + 1024;
    const float* vbase = qbase + 2048;

    const uint32_t sK = (uint32_t)__cvta_generic_to_shared(Kbase);
    const uint32_t sV = (uint32_t)__cvta_generic_to_shared(Vbase);

    auto load_kv = [&](int j, int s) {
        for (int e = tid; e < FBC * 16; e += 256) {
            int r = e >> 4, c4 = (e & 15) << 2;
            cp16(sK + (uint32_t)(s * KV_TILE + r * KSTR + c4) * 4u,
                 kbase + (long long)(j * FBC + r) * 3072 + c4);
        }
        for (int e = tid; e < FBC * 16; e += 256) {
            int r = e >> 4, c4 = (e & 15) << 2;
            cp16(sV + (uint32_t)(s * V_TILE + r * VSTR + c4) * 4u,
                 vbase + (long long)(j * FBC + r) * 3072 + c4);
        }
        cp_commit();
    };

    // stage Q tile [128 x 64] and first K/V block
    {
        uint32_t sQ = (uint32_t)__cvta_generic_to_shared(Ps);
        for (int e = tid; e < FBR * 16; e += 256) {
            int r = e >> 4, c4 = (e & 15) << 2;
            cp16(sQ + (uint32_t)(r * QSTR + c4) * 4u,
                 qbase + (long long)(ib * FBR + r) * 3072 + c4);
        }
        cp_commit();
        load_kv(0, 0);                        // group for j=0
        cp_wait<1>();                         // Q done (K/V j0 may be in flight)
    }
    __syncthreads();

    // Q fragments in regs for all j
    uint32_t qf[8][4];
    {
        const float* Qb = Ps + (w * 16 + qr) * QSTR;
#pragma unroll
        for (int ks = 0; ks < 8; ks++) {
            qf[ks][0] = __float_as_uint(Qb[ks * 8 + qc]);
            qf[ks][1] = __float_as_uint(Qb[8 * QSTR + ks * 8 + qc]);
            qf[ks][2] = __float_as_uint(Qb[ks * 8 + qc + 4]);
            qf[ks][3] = __float_as_uint(Qb[8 * QSTR + ks * 8 + qc + 4]);
        }
    }

    float m0 = -1e30f, m1 = -1e30f, l0 = 0.f, l1 = 0.f;
    float o[8][4];
#pragma unroll
    for (int i = 0; i < 8; i++)
#pragma unroll
        for (int v = 0; v < 4; v++) o[i][v] = 0.f;

    const int row0 = ib * FBR + w * 16 + qr;
    const int jmax = 2 * ib + 2;

    for (int j = 0; j < jmax; j++) {
        const int s = j & 1;
        if (j + 1 < jmax) {
            load_kv(j + 1, s ^ 1);            // prefetch into other buffer
            cp_wait<1>();                     // buffer s (issued last iter) done
        } else {
            cp_wait<0>();
        }
        __syncthreads();                      // buffer s visible to all threads

        const float* Ks = Kbase + s * KV_TILE;
        const float* Vs = Vbase + s * V_TILE;

        // S = Q . K^T
        float sfr[8][4];
#pragma unroll
        for (int nt = 0; nt < 8; nt++)
#pragma unroll
            for (int v = 0; v < 4; v++) sfr[nt][v] = 0.f;
#pragma unroll
        for (int ks = 0; ks < 8; ks++) {
            uint32_t bf[8][2];
#pragma unroll
            for (int nt = 0; nt < 8; nt++) {
                const float* Kr = Ks + (nt * 8 + qr) * KSTR + ks * 8 + qc;
                bf[nt][0] = __float_as_uint(Kr[0]);
                bf[nt][1] = __float_as_uint(Kr[4]);
            }
#pragma unroll
            for (int nt = 0; nt < 8; nt++)
                mma8(sfr[nt], qf[ks], bf[nt]);
        }

        // scale + causal mask
#pragma unroll
        for (int nt = 0; nt < 8; nt++) {
            int c0 = j * FBC + nt * 8 + 2 * qc;
#pragma unroll
            for (int v = 0; v < 4; v++) {
                int cg = c0 + (v & 1);
                int rg = row0 + (v >> 1) * 8;
                float val = sfr[nt][v] * SCALE;
                sfr[nt][v] = (cg <= rg) ? val : -1e30f;
            }
        }

        // online softmax
        float rm0 = -1e30f, rm1 = -1e30f;
#pragma unroll
        for (int nt = 0; nt < 8; nt++) {
            rm0 = fmaxf(rm0, fmaxf(sfr[nt][0], sfr[nt][1]));
            rm1 = fmaxf(rm1, fmaxf(sfr[nt][2], sfr[nt][3]));
        }
        rm0 = fmaxf(rm0, __shfl_xor_sync(0xffffffffu, rm0, 1));
        rm0 = fmaxf(rm0, __shfl_xor_sync(0xffffffffu, rm0, 2));
        rm1 = fmaxf(rm1, __shfl_xor_sync(0xffffffffu, rm1, 1));
        rm1 = fmaxf(rm1, __shfl_xor_sync(0xffffffffu, rm1, 2));
        float nm0 = fmaxf(m0, rm0), nm1 = fmaxf(m1, rm1);
        float a0 = __expf(m0 - nm0), a1 = __expf(m1 - nm1);

        float* Pr = Ps + (w * 16 + qr) * PSTR;
        float sum0 = 0.f, sum1 = 0.f;
#pragma unroll
        for (int nt = 0; nt < 8; nt++) {
            float p0 = __expf(sfr[nt][0] - nm0);
            float p1 = __expf(sfr[nt][1] - nm0);
            float p2 = __expf(sfr[nt][2] - nm1);
            float p3 = __expf(sfr[nt][3] - nm1);
            sum0 += p0 + p1; sum1 += p2 + p3;
            int c = nt * 8 + 2 * qc;
            Pr[c]     = rnd_tf32(p0);
            Pr[c + 1] = rnd_tf32(p1);
            Pr[8 * PSTR + c]     = rnd_tf32(p2);
            Pr[8 * PSTR + c + 1] = rnd_tf32(p3);
        }
        sum0 += __shfl_xor_sync(0xffffffffu, sum0, 1);
        sum0 += __shfl_xor_sync(0xffffffffu, sum0, 2);
        sum1 += __shfl_xor_sync(0xffffffffu, sum1, 1);
        sum1 += __shfl_xor_sync(0xffffffffu, sum1, 2);
        l0 = l0 * a0 + sum0;
        l1 = l1 * a1 + sum1;
        m0 = nm0; m1 = nm1;
#pragma unroll
        for (int nto = 0; nto < 8; nto++) {
            o[nto][0] *= a0; o[nto][1] *= a0;
            o[nto][2] *= a1; o[nto][3] *= a1;
        }
        __syncwarp();   // P visible within warp

        // O += P . V
#pragma unroll
        for (int ks = 0; ks < 8; ks++) {
            uint32_t pf[4];
            pf[0] = __float_as_uint(Pr[ks * 8 + qc]);
            pf[1] = __float_as_uint(Pr[8 * PSTR + ks * 8 + qc]);
            pf[2] = __float_as_uint(Pr[ks * 8 + qc + 4]);
            pf[3] = __float_as_uint(Pr[8 * PSTR + ks * 8 + qc + 4]);
#pragma unroll
            for (int nto = 0; nto < 8; nto++) {
                uint32_t bf2[2];
                bf2[0] = __float_as_uint(Vs[(ks * 8 + qc) * VSTR + nto * 8 + qr]);
                bf2[1] = __float_as_uint(Vs[(ks * 8 + qc + 4) * VSTR + nto * 8 + qr]);
                mma8(o[nto], pf, bf2);
            }
        }
        __syncthreads();   // all warps done reading buffer s before it's reloaded
    }

    float i0 = 1.f / l0, i1 = 1.f / l1;
    float* arow0 = att + (long long)(b * Tn + row0) * En + h * 64;
    float* arow1 = arow0 + 8ll * En;
#pragma unroll
    for (int nto = 0; nto < 8; nto++) {
        int c = nto * 8 + 2 * qc;
        float2 v0 = { rnd_tf32(o[nto][0] * i0), rnd_tf32(o[nto][1] * i0) };
        float2 v1 = { rnd_tf32(o[nto][2] * i1), rnd_tf32(o[nto][3] * i1) };
        *(float2*)(arow0 + c) = v0;
        *(float2*)(arow1 + c) = v1;
    }
}

// ---------------- weight prep ----------------
__global__ void round_copy(const float* __restrict__ src, float* __restrict__ dst, long long n4)
{
    long long i = (long long)blockIdx.x * blockDim.x + threadIdx.x;
    if (i >= n4) return;
    float4 v = ((const float4*)src)[i];
    v.x = rnd_tf32(v.x); v.y = rnd_tf32(v.y); v.z = rnd_tf32(v.z); v.w = rnd_tf32(v.w);
    ((float4*)dst)[i] = v;
}

__global__ void repack_qkv(const float* __restrict__ wq,
                           const float* __restrict__ wk,
                           const float* __restrict__ wv,
                           float* __restrict__ dst)
{
    int le = blockIdx.x;            // l*1024 + e
    int l = le >> 10, e = le & 1023;
    const float* srcs[3] = { wq, wk, wv };
    float* drow = dst + (long long)le * 3072;
    for (int s = 0; s < 3; s++) {
        const float* ws = srcs[s];
        for (int idx = threadIdx.x; idx < 1024; idx += 256) {
            int h = idx >> 6, d = idx & 63;
            float v = ws[(((long long)l * Hn + h) * En + e) * Dn + d];
            drow[s * 1024 + idx] = rnd_tf32(v);
        }
    }
}

__global__ void pad_lm_w(const float* __restrict__ src, float* __restrict__ dst)
{
    int r = blockIdx.x;
    const float* s = src + (long long)r * Vn;
    float* d = dst + (long long)r * VPAD;
    for (int c = threadIdx.x; c < VPAD; c += blockDim.x)
        d[c] = (c < Vn) ? rnd_tf32(s[c]) : 0.f;
}

// ---------------- elementwise ----------------
__global__ void embed_kernel(const int* __restrict__ idx,
                             const float* __restrict__ tok,
                             const float* __restrict__ pos,
                             float* __restrict__ x)
{
    int bt = blockIdx.x;
    int t = bt % Tn;
    int token = idx[bt];
    const float4* tr = (const float4*)(tok + (long long)token * En);
    const float4* pr = (const float4*)(pos + (long long)t * En);
    float4* xr = (float4*)(x + (long long)bt * En);
    int e = threadIdx.x;
    float4 a = tr[e], b = pr[e];
    xr[e] = make_float4(a.x + b.x, a.y + b.y, a.z + b.z, a.w + b.w);
}

__global__ void ln_kernel(const float* __restrict__ x,
                          const float* __restrict__ g,
                          const float* __restrict__ b,
                          float* __restrict__ out)
{
    int row = blockIdx.x;
    int tid = threadIdx.x, lane = tid & 31, w = tid >> 5;
    const float4* xr = (const float4*)(x + (long long)row * En);
    float4 v = xr[tid];
    __shared__ float red[8];

    float s = v.x + v.y + v.z + v.w;
#pragma unroll
    for (int o = 16; o > 0; o >>= 1) s += __shfl_xor_sync(0xffffffffu, s, o);
    if (lane == 0) red[w] = s;
    __syncthreads();
    float mu = (red[0]+red[1]+red[2]+red[3]+red[4]+red[5]+red[6]+red[7]) * (1.f / En);

    float dx = v.x - mu, dy = v.y - mu, dz = v.z - mu, dw = v.w - mu;
    float vv = dx*dx + dy*dy + dz*dz + dw*dw;
#pragma unroll
    for (int o = 16; o > 0; o >>= 1) vv += __shfl_xor_sync(0xffffffffu, vv, o);
    __syncthreads();
    if (lane == 0) red[w] = vv;
    __syncthreads();
    float rstd = rsqrtf((red[0]+red[1]+red[2]+red[3]+red[4]+red[5]+red[6]+red[7]) * (1.f / En) + EPS);

    const float4 gg = ((const float4*)g)[tid];
    const float4 bb = ((const float4*)b)[tid];
    float4 o4;
    o4.x = rnd_tf32(dx * rstd * gg.x + bb.x);
    o4.y = rnd_tf32(dy * rstd * gg.y + bb.y);
    o4.z = rnd_tf32(dz * rstd * gg.z + bb.z);
    o4.w = rnd_tf32(dw * rstd * gg.w + bb.w);
    ((float4*)(out + (long long)row * En))[tid] = o4;
}

__global__ void nll_kernel(const float* __restrict__ logits,
                           const int* __restrict__ targets,
                           float* __restrict__ rownll)
{
    int row = blockIdx.x;
    const float* lr = logits + (long long)row * Vn;
    int tid = threadIdx.x;
    float m = -1e30f, s = 0.f;
    for (int i = tid; i < Vn; i += 256) {
        float v = lr[i];
        if (v > m) { s = s * __expf(m - v) + 1.f; m = v; }
        else       { s += __expf(v - m); }
    }
    __shared__ float sm2[256], ss[256];
    sm2[tid] = m; ss[tid] = s;
    __syncthreads();
    for (int o = 128; o > 0; o >>= 1) {
        if (tid < o) {
            float m2 = sm2[tid + o], s2 = ss[tid + o];
            float M = fmaxf(sm2[tid], m2);
            ss[tid] = ss[tid] * __expf(sm2[tid] - M) + s2 * __expf(m2 - M);
            sm2[tid] = M;
        }
        __syncthreads();
    }
    if (tid == 0) {
        float lse = sm2[0] + logf(ss[0]);
        rownll[row] = -(lr[targets[row]] - lse);
    }
}

__global__ void mean_kernel(const float* __restrict__ rownll, float* __restrict__ out)
{
    __shared__ float red[256];
    int tid = threadIdx.x;
    float s = 0.f;
    for (int i = tid; i < BT; i += 256) s += rownll[i];
    red[tid] = s; __syncthreads();
    for (int o = 128; o > 0; o >>= 1) { if (tid < o) red[tid] += red[tid + o]; __syncthreads(); }
    if (tid == 0) out[0] = red[0] / (float)BT;
}

// ---------------- host launcher ----------------
static constexpr int SMEM_A = 2 * (128 * 36 + 32 * 136) * 4;   // 71680

extern "C" void kernel_launch(void* const* d_in, const int* in_sizes, int n_in,
                              void* d_out, int out_size)
{
    const int*   idx     = (const int*)  d_in[0];
    const int*   targets = (const int*)  d_in[1];
    const float* tok_emb = (const float*)d_in[2];
    const float* pos_emb = (const float*)d_in[3];
    const float* wq      = (const float*)d_in[4];
    const float* wk      = (const float*)d_in[5];
    const float* wv      = (const float*)d_in[6];
    const float* w_proj  = (const float*)d_in[7];
    const float* b_proj  = (const float*)d_in[8];
    const float* ln1_g   = (const float*)d_in[9];
    const float* ln1_b   = (const float*)d_in[10];
    const float* ln2_g   = (const float*)d_in[11];
    const float* ln2_b   = (const float*)d_in[12];
    const float* ff_w1   = (const float*)d_in[13];
    const float* ff_b1   = (const float*)d_in[14];
    const float* ff_w2   = (const float*)d_in[15];
    const float* ff_b2   = (const float*)d_in[16];
    const float* lnf_g   = (const float*)d_in[17];
    const float* lnf_b   = (const float*)d_in[18];
    const float* lm_w    = (const float*)d_in[19];
    const float* lm_b    = (const float*)d_in[20];
    float* out = (float*)d_out;

    float *x, *h, *qkv, *att, *ff, *wqkv, *wprj, *wff1, *wff2, *wpad, *rownll;
    cudaGetSymbolAddress((void**)&x,      g_x);
    cudaGetSymbolAddress((void**)&h,      g_h);
    cudaGetSymbolAddress((void**)&qkv,    g_qkv);
    cudaGetSymbolAddress((void**)&att,    g_att);
    cudaGetSymbolAddress((void**)&ff,     g_ff);
    cudaGetSymbolAddress((void**)&wqkv,   g_wqkv);
    cudaGetSymbolAddress((void**)&wprj,   g_wprj);
    cudaGetSymbolAddress((void**)&wff1,   g_wff1);
    cudaGetSymbolAddress((void**)&wff2,   g_wff2);
    cudaGetSymbolAddress((void**)&wpad,   g_wpad);
    cudaGetSymbolAddress((void**)&rownll, g_rownll);

    auto kA = gemm_tf32<128, 128, 64, 32, 32>;   // 8 warps / 256 threads (proven 9256us config)
    cudaFuncSetAttribute(kA, cudaFuncAttributeMaxDynamicSharedMemorySize, SMEM_A);
    cudaFuncSetAttribute(flash_kernel, cudaFuncAttributeMaxDynamicSharedMemorySize, FLASH_SMEM);

    // ---- weight prep ----
    repack_qkv<<<Ln * En, 256>>>(wq, wk, wv, wqkv);
    {
        long long n4;
        n4 = (long long)Ln * En * En / 4;
        round_copy<<<(unsigned)((n4 + 255) / 256), 256>>>(w_proj, wprj, n4);
        n4 = (long long)Ln * En * FFn / 4;
        round_copy<<<(unsigned)((n4 + 255) / 256), 256>>>(ff_w1, wff1, n4);
        round_copy<<<(unsigned)((n4 + 255) / 256), 256>>>(ff_w2, wff2, n4);
    }
    pad_lm_w<<<En, 256>>>(lm_w, wpad);

    // x = tok_emb[idx] + pos_emb
    embed_kernel<<<BT, 256>>>(idx, tok_emb, pos_emb, x);

    for (int l = 0; l < Ln; l++) {
        // h = LN1(x)
        ln_kernel<<<BT, 256>>>(x, ln1_g + (long long)l * En, ln1_b + (long long)l * En, h);

        // qkv = h @ Wqkv  [4096 x 3072 x 1024]
        kA<<<dim3(BT / 128, 3 * En / 128), 256, SMEM_A>>>(
            BT, 3 * En, En,
            h, En,
            wqkv + (long long)l * En * 3 * En, 3 * En,
            qkv, 3 * En,
            nullptr, nullptr, 2);

        // fused causal attention (double-buffered K/V)
        flash_kernel<<<dim3(8, Bn * Hn), 256, FLASH_SMEM>>>(qkv, att);

        // x = x + att @ w_proj + b_proj
        kA<<<dim3(BT / 128, En / 128), 256, SMEM_A>>>(
            BT, En, En,
            att, En,
            wprj + (long long)l * En * En, En,
            x, En,
            b_proj + (long long)l * En, x, 0);

        // h = LN2(x)
        ln_kernel<<<BT, 256>>>(x, ln2_g + (long long)l * En, ln2_b + (long long)l * En, h);

        // ff = relu(h @ ff_w1 + ff_b1)
        kA<<<dim3(BT / 128, FFn / 128), 256, SMEM_A>>>(
            BT, FFn, En,
            h, En,
            wff1 + (long long)l * En * FFn, FFn,
            ff, FFn,
            ff_b1 + (long long)l * FFn, nullptr, 3);

        // x = x + ff @ ff_w2 + ff_b2
        kA<<<dim3(BT / 128, En / 128), 256, SMEM_A>>>(
            BT, En, FFn,
            ff, FFn,
            wff2 + (long long)l * FFn * En, En,
            x, En,
            ff_b2 + (long long)l * En, x, 0);
    }

    // h = LN_f(x)
    ln_kernel<<<BT, 256>>>(x, lnf_g, lnf_b, h);

    // logits = h @ lm_w + lm_b
    kA<<<dim3(BT / 128, VPAD / 128), 256, SMEM_A>>>(
        BT, Vn, En,
        h, En,
        wpad, VPAD,
        out, Vn,
        lm_b, nullptr, 0);

    // loss
    if ((long long)out_size > (long long)BT * Vn) {
        nll_kernel<<<BT, 256>>>(out, targets, rownll);
        mean_kernel<<<1, 256>>>(rownll, out + (long long)BT * Vn);
    }
}